// round 3
// baseline (speedup 1.0000x reference)
#include <cuda_runtime.h>
#include <math.h>

#define Bb 4
#define Ss 2048
#define Dd 256
#define Rr (Bb*Ss)

// ------------------- scratch (device globals; no allocation) ---------------
__device__ __align__(16) float g_x[Rr*Dd];   // normalized context
__device__ __align__(16) float g_u[Rr*Dd];   // U[r] = M x_r
__device__ __align__(16) float g_M[Dd*Dd];   // M = Wq^T Wk
__device__ float g_c1[Dd], g_c2[Dd];
__device__ float g_c0;
__device__ float g_dotp[Rr], g_dotm[Rr], g_A1[Rr], g_A2[Rr];
__device__ float g_pp[Rr], g_pm[Rr], g_ps[Rr], g_diag[Rr];
__device__ double g_l[Rr], g_P[Rr];

// ------------------- K1: LayerNorm (unbiased std, eps on std) --------------
__global__ void ln_kernel(const float* __restrict__ ctx,
                          const float* __restrict__ la,
                          const float* __restrict__ lb) {
    int r = blockIdx.x, t = threadIdx.x;
    __shared__ float red[16];
    int lane = t & 31, w = t >> 5;

    float v = ctx[(size_t)r*Dd + t];

    float s = v;
    #pragma unroll
    for (int o = 16; o; o >>= 1) s += __shfl_down_sync(0xffffffffu, s, o);
    if (lane == 0) red[w] = s;
    __syncthreads();
    if (t == 0) { float x = 0.f; for (int k = 0; k < 8; ++k) x += red[k]; red[8] = x; }
    __syncthreads();
    float mean = red[8] * (1.0f/Dd);

    float d = v - mean;
    float sq = d*d;
    #pragma unroll
    for (int o = 16; o; o >>= 1) sq += __shfl_down_sync(0xffffffffu, sq, o);
    if (lane == 0) red[w] = sq;
    __syncthreads();
    if (t == 0) { float x = 0.f; for (int k = 0; k < 8; ++k) x += red[k]; red[9] = x; }
    __syncthreads();
    float var = red[9] * (1.0f/(Dd-1));
    float inv = 1.0f / (sqrtf(var) + 1e-6f);

    g_x[(size_t)r*Dd + t] = la[t]*d*inv + lb[t];
}

// ------------------- K2: c1 = Wq^T bk, c2 = Wk^T bq, c0 = bq.bk ------------
__global__ void bias_kernel(const float* __restrict__ Wq, const float* __restrict__ Wk,
                            const float* __restrict__ bq, const float* __restrict__ bk) {
    int t = threadIdx.x;
    float a1 = 0.f, a2 = 0.f;
    for (int f = 0; f < Dd; ++f) {
        a1 += Wq[f*Dd + t] * bk[f];
        a2 += Wk[f*Dd + t] * bq[f];
    }
    g_c1[t] = a1; g_c2[t] = a2;
    __shared__ float red[256];
    red[t] = bq[t] * bk[t];
    __syncthreads();
    for (int s = 128; s; s >>= 1) { if (t < s) red[t] += red[t+s]; __syncthreads(); }
    if (t == 0) g_c0 = red[0];
}

// ------------------- K3: M[d,e] = sum_f Wq[f,d] Wk[f,e] --------------------
__global__ void m_kernel(const float* __restrict__ Wq, const float* __restrict__ Wk) {
    __shared__ float sq[16][17], sk[16][17];
    int tx = threadIdx.x, ty = threadIdx.y;
    int d = blockIdx.y*16 + ty;
    int e = blockIdx.x*16 + tx;
    float acc = 0.f;
    for (int f0 = 0; f0 < Dd; f0 += 16) {
        sq[ty][tx] = Wq[(f0+ty)*Dd + blockIdx.y*16 + tx];
        sk[ty][tx] = Wk[(f0+ty)*Dd + blockIdx.x*16 + tx];
        __syncthreads();
        #pragma unroll
        for (int f = 0; f < 16; ++f) acc += sq[f][ty] * sk[f][tx];
        __syncthreads();
    }
    g_M[d*Dd + e] = acc;
}

// ------------------- K4: U = X @ M^T  (C[r,d] = sum_e X[r,e] M[d,e]) -------
__global__ void gemm_kernel() {
    __shared__ __align__(16) float Xs[16][68];
    __shared__ __align__(16) float Ms[16][68];
    int tid = threadIdx.x;
    int tx = tid & 15, ty = tid >> 4;
    int r0 = blockIdx.y * 64;
    int d0 = blockIdx.x * 64;
    int lrow = tid >> 2;
    int lk = (tid & 3) * 4;
    float acc[4][4] = {};
    for (int e0 = 0; e0 < Dd; e0 += 16) {
        float4 xa = *(const float4*)&g_x[(size_t)(r0+lrow)*Dd + e0 + lk];
        float4 ma = *(const float4*)&g_M[(d0+lrow)*Dd + e0 + lk];
        Xs[lk+0][lrow] = xa.x; Xs[lk+1][lrow] = xa.y; Xs[lk+2][lrow] = xa.z; Xs[lk+3][lrow] = xa.w;
        Ms[lk+0][lrow] = ma.x; Ms[lk+1][lrow] = ma.y; Ms[lk+2][lrow] = ma.z; Ms[lk+3][lrow] = ma.w;
        __syncthreads();
        #pragma unroll
        for (int k = 0; k < 16; ++k) {
            float4 a = *(const float4*)&Xs[k][ty*4];
            float4 b = *(const float4*)&Ms[k][tx*4];
            float av[4] = {a.x, a.y, a.z, a.w};
            float bv[4] = {b.x, b.y, b.z, b.w};
            #pragma unroll
            for (int i2 = 0; i2 < 4; ++i2)
                #pragma unroll
                for (int j2 = 0; j2 < 4; ++j2) acc[i2][j2] += av[i2]*bv[j2];
        }
        __syncthreads();
    }
    #pragma unroll
    for (int i2 = 0; i2 < 4; ++i2) {
        float4 o = make_float4(acc[i2][0], acc[i2][1], acc[i2][2], acc[i2][3]);
        *(float4*)&g_u[(size_t)(r0+ty*4+i2)*Dd + d0 + tx*4] = o;
    }
}

// ------------------- K5: per-row dots --------------------------------------
__global__ void dots_kernel() {
    int r = blockIdx.x, t = threadIdx.x;
    int i = r & (Ss-1);
    float xv = g_x[(size_t)r*Dd + t];
    float dp = (i < Ss-1) ? xv * g_u[(size_t)(r+1)*Dd + t] : 0.f;
    float dm = (i > 0)    ? xv * g_u[(size_t)(r-1)*Dd + t] : 0.f;
    float a1 = xv * g_c1[t];
    float a2 = xv * g_c2[t];
    __shared__ float red[4][8];
    int lane = t & 31, w = t >> 5;
    #pragma unroll
    for (int o = 16; o; o >>= 1) {
        dp += __shfl_down_sync(0xffffffffu, dp, o);
        dm += __shfl_down_sync(0xffffffffu, dm, o);
        a1 += __shfl_down_sync(0xffffffffu, a1, o);
        a2 += __shfl_down_sync(0xffffffffu, a2, o);
    }
    if (lane == 0) { red[0][w] = dp; red[1][w] = dm; red[2][w] = a1; red[3][w] = a2; }
    __syncthreads();
    if (t == 0) {
        float s0 = 0, s1 = 0, s2 = 0, s3 = 0;
        for (int k = 0; k < 8; ++k) { s0 += red[0][k]; s1 += red[1][k]; s2 += red[2][k]; s3 += red[3][k]; }
        g_dotp[r] = s0; g_dotm[r] = s1; g_A1[r] = s2; g_A2[r] = s3;
    }
}

// ------------------- K6: masked 2-entry softmax probabilities --------------
__global__ void prob_kernel(const int* __restrict__ eos) {
    int r = blockIdx.x*256 + threadIdx.x;
    if (r >= Rr) return;
    int b = r >> 11, i = r & (Ss-1);
    const int* erow = eos + (size_t)b*Ss*Ss + (size_t)i*Ss;
    bool ap = (i < Ss-1) && (erow[i+1] != 0);
    bool am = (i > 0)    && (erow[i-1] != 0);
    float pp, pm, ps;
    if (!ap && !am) {
        pp = pm = ps = 1.0f/(float)Ss;   // fully masked row -> uniform softmax
    } else {
        ps = 0.f;
        if (ap && am) {
            float c0 = g_c0;
            float sp = (g_dotp[r] + g_A1[r] + g_A2[r+1] + c0) * (1.0f/256.0f);
            float sm = (g_dotm[r] + g_A1[r] + g_A2[r-1] + c0) * (1.0f/256.0f);
            float m = fmaxf(sp, sm);
            float ep = expf(sp - m), em = expf(sm - m);
            float inv = 1.0f/(ep + em);
            pp = ep*inv; pm = em*inv;
        } else if (ap) { pp = 1.f; pm = 0.f; }
        else           { pp = 0.f; pm = 1.f; }
    }
    g_pp[r] = pp; g_pm[r] = pm; g_ps[r] = ps;
}

// ------------------- K7: l_i and diagonal values ---------------------------
__global__ void ldiag_kernel(const float* __restrict__ prior) {
    int r = blockIdx.x*256 + threadIdx.x;
    if (r >= Rr) return;
    int b = r >> 11, i = r & (Ss-1);
    const float* prow = prior + (size_t)b*Ss*Ss + (size_t)i*Ss;
    if (i < Ss-1) {
        float n1 = sqrtf(g_pp[r]*g_pm[r+1] + 1e-9f);
        float pr = prow[i+1];
        float nb = pr + (1.0f - pr)*n1;
        g_l[r] = log((double)nb + 1e-9);
    } else {
        g_l[r] = 0.0;
    }
    float ps = g_ps[r];
    float nd = sqrtf(ps*ps + 1e-9f);
    float pr = prow[i];
    g_diag[r] = pr + (1.0f - pr)*nd;
}

// ------------------- K8: per-batch exclusive prefix sum (f64) --------------
__global__ void scan_kernel() {
    __shared__ double ps[1024];
    int b = blockIdx.x, t = threadIdx.x;
    int base = b*Ss;
    double a0 = g_l[base + 2*t];
    double a1 = g_l[base + 2*t + 1];
    double s = a0 + a1;
    ps[t] = s;
    __syncthreads();
    for (int off = 1; off < 1024; off <<= 1) {
        double v = (t >= off) ? ps[t - off] : 0.0;
        __syncthreads();
        ps[t] += v;
        __syncthreads();
    }
    double excl = ps[t] - s;
    g_P[base + 2*t]     = excl;
    g_P[base + 2*t + 1] = excl + a0;
}

// ------------------- K9: banded output -------------------------------------
__global__ void out_kernel(float* __restrict__ out) {
    int r = blockIdx.x;
    int b = r >> 11, i = r & (Ss-1);
    const double* P = g_P + b*Ss;
    double Pi = P[i];
    const double T = 46.0;   // exp(-46) ~ 1e-20 << 1e-9 floor

    // largest j >= i with Pi - P[j] <= T  (P non-increasing up to 1e-9 wiggle)
    int lo2 = i, hi2 = Ss-1;
    while (lo2 < hi2) {
        int mid = (lo2 + hi2 + 1) >> 1;
        if (Pi - P[mid] <= T) lo2 = mid; else hi2 = mid - 1;
    }
    int hi = lo2;
    // smallest j <= i with P[j] - Pi <= T
    int a = 0, b2 = i;
    while (a < b2) {
        int mid = (a + b2) >> 1;
        if (P[mid] - Pi <= T) b2 = mid; else a = mid + 1;
    }
    int lo = a;

    float dg = g_diag[r];
    float* orow = out + (size_t)r*Ss;
    for (int j = threadIdx.x; j < Ss; j += blockDim.x) {
        float v;
        if (j < lo || j > hi)      v = 1e-9f;
        else if (j == i)           v = dg;
        else {
            double e = (j > i) ? (P[j] - Pi) : (Pi - P[j]);
            v = expf((float)e) + 1e-9f;
        }
        orow[j] = v;
    }
}

// ------------------- launch -------------------------------------------------
extern "C" void kernel_launch(void* const* d_in, const int* in_sizes, int n_in,
                              void* d_out, int out_size) {
    const float* ctx   = (const float*)d_in[0];
    const float* prior = (const float*)d_in[1];
    const float* Wq    = (const float*)d_in[2];
    const float* bq    = (const float*)d_in[3];
    const float* Wk    = (const float*)d_in[4];
    const float* bk    = (const float*)d_in[5];
    const float* la    = (const float*)d_in[6];
    const float* lb    = (const float*)d_in[7];
    const int*   eos   = (const int*)d_in[8];
    float* out = (float*)d_out;

    ln_kernel<<<Rr, 256>>>(ctx, la, lb);
    bias_kernel<<<1, 256>>>(Wq, Wk, bq, bk);
    m_kernel<<<dim3(16,16), dim3(16,16)>>>(Wq, Wk);
    gemm_kernel<<<dim3(Dd/64, Rr/64), 256>>>();
    dots_kernel<<<Rr, 256>>>();
    prob_kernel<<<Rr/256, 256>>>(eos);
    ldiag_kernel<<<Rr/256, 256>>>(prior);
    scan_kernel<<<Bb, 1024>>>();
    out_kernel<<<Rr, 256>>>(out);
}

// round 5
// speedup vs baseline: 2.1369x; 2.1369x over previous
#include <cuda_runtime.h>
#include <math.h>

#define Bb 4
#define Ss 2048
#define Dd 256
#define Rr (Bb*Ss)

// ------------------- scratch (device globals; no allocation) ---------------
__device__ __align__(16) float g_x[Rr*Dd];   // normalized context
__device__ __align__(16) float g_u[Rr*Dd];   // U[r] = M x_r
__device__ __align__(16) float g_M[Dd*Dd];   // M = Wq^T Wk
__device__ __align__(16) float g_c1[Dd], g_c2[Dd];
__device__ float g_c0;
__device__ float g_dotp[Rr], g_dotm[Rr], g_A1[Rr], g_A2[Rr];
__device__ float g_diag[Rr];
__device__ double g_l[Rr], g_P[Rr];
__device__ int g_lo[Rr], g_hi[Rr];

// ------------------- K1: LayerNorm, warp per row ---------------------------
__global__ void ln_kernel(const float* __restrict__ ctx,
                          const float* __restrict__ la,
                          const float* __restrict__ lb) {
    int tid = threadIdx.x;
    int w = tid >> 5, lane = tid & 31;
    int r = blockIdx.x * 8 + w;
    const float* src = ctx + (size_t)r * Dd;

    float4 v0 = *(const float4*)&src[lane*4];
    float4 v1 = *(const float4*)&src[128 + lane*4];

    float s = v0.x+v0.y+v0.z+v0.w + v1.x+v1.y+v1.z+v1.w;
    #pragma unroll
    for (int o = 16; o; o >>= 1) s += __shfl_xor_sync(0xffffffffu, s, o);
    float mean = s * (1.0f/Dd);

    float d0x=v0.x-mean, d0y=v0.y-mean, d0z=v0.z-mean, d0w=v0.w-mean;
    float d1x=v1.x-mean, d1y=v1.y-mean, d1z=v1.z-mean, d1w=v1.w-mean;
    float sq = d0x*d0x+d0y*d0y+d0z*d0z+d0w*d0w + d1x*d1x+d1y*d1y+d1z*d1z+d1w*d1w;
    #pragma unroll
    for (int o = 16; o; o >>= 1) sq += __shfl_xor_sync(0xffffffffu, sq, o);
    float inv = 1.0f / (sqrtf(sq * (1.0f/(Dd-1))) + 1e-6f);

    float4 a0 = *(const float4*)&la[lane*4];
    float4 a1 = *(const float4*)&la[128 + lane*4];
    float4 b0 = *(const float4*)&lb[lane*4];
    float4 b1 = *(const float4*)&lb[128 + lane*4];
    float* dst = g_x + (size_t)r * Dd;
    *(float4*)&dst[lane*4] = make_float4(a0.x*d0x*inv + b0.x, a0.y*d0y*inv + b0.y,
                                         a0.z*d0z*inv + b0.z, a0.w*d0w*inv + b0.w);
    *(float4*)&dst[128 + lane*4] = make_float4(a1.x*d1x*inv + b1.x, a1.y*d1y*inv + b1.y,
                                               a1.z*d1z*inv + b1.z, a1.w*d1w*inv + b1.w);
}

// ------------------- K2: c1 = Wq^T bk, c2 = Wk^T bq, c0 = bq.bk ------------
__global__ void bias_kernel(const float* __restrict__ Wq, const float* __restrict__ Wk,
                            const float* __restrict__ bq, const float* __restrict__ bk) {
    int t = threadIdx.x;
    float a1 = 0.f, a2 = 0.f;
    for (int f = 0; f < Dd; ++f) {
        a1 += Wq[f*Dd + t] * bk[f];
        a2 += Wk[f*Dd + t] * bq[f];
    }
    g_c1[t] = a1; g_c2[t] = a2;
    __shared__ float red[256];
    red[t] = bq[t] * bk[t];
    __syncthreads();
    for (int s = 128; s; s >>= 1) { if (t < s) red[t] += red[t+s]; __syncthreads(); }
    if (t == 0) g_c0 = red[0];
}

// ------------------- K3: M[d,e] = sum_f Wq[f,d] Wk[f,e] --------------------
__global__ void m_kernel(const float* __restrict__ Wq, const float* __restrict__ Wk) {
    __shared__ float sq[16][17], sk[16][17];
    int tx = threadIdx.x, ty = threadIdx.y;
    int d = blockIdx.y*16 + ty;
    int e = blockIdx.x*16 + tx;
    float acc = 0.f;
    for (int f0 = 0; f0 < Dd; f0 += 16) {
        sq[ty][tx] = Wq[(f0+ty)*Dd + blockIdx.y*16 + tx];
        sk[ty][tx] = Wk[(f0+ty)*Dd + blockIdx.x*16 + tx];
        __syncthreads();
        #pragma unroll
        for (int f = 0; f < 16; ++f) acc += sq[f][ty] * sk[f][tx];
        __syncthreads();
    }
    g_M[d*Dd + e] = acc;
}

// ------------------- K4: U = X @ M^T, 128x64 tile, 8x4 micro ---------------
__global__ void gemm_kernel() {
    __shared__ __align__(16) float As[16][132];
    __shared__ __align__(16) float Bs[16][68];
    int tid = threadIdx.x;
    int tx = tid & 15;     // 4 output cols each
    int ty = tid >> 4;     // 8 output rows each
    int d0 = blockIdx.x * 64;
    int r0 = blockIdx.y * 128;
    float acc[8][4] = {};
    for (int e0 = 0; e0 < Dd; e0 += 16) {
        #pragma unroll
        for (int s = 0; s < 2; ++s) {
            int idx = tid + s*256;
            int row = idx >> 2, seg = idx & 3;
            float4 v = *(const float4*)&g_x[(size_t)(r0+row)*Dd + e0 + seg*4];
            As[seg*4+0][row] = v.x; As[seg*4+1][row] = v.y;
            As[seg*4+2][row] = v.z; As[seg*4+3][row] = v.w;
        }
        {
            int row = tid >> 2, seg = tid & 3;
            float4 v = *(const float4*)&g_M[(size_t)(d0+row)*Dd + e0 + seg*4];
            Bs[seg*4+0][row] = v.x; Bs[seg*4+1][row] = v.y;
            Bs[seg*4+2][row] = v.z; Bs[seg*4+3][row] = v.w;
        }
        __syncthreads();
        #pragma unroll
        for (int k = 0; k < 16; ++k) {
            float4 a0 = *(const float4*)&As[k][ty*8];
            float4 a1 = *(const float4*)&As[k][ty*8+4];
            float4 bb = *(const float4*)&Bs[k][tx*4];
            float av[8] = {a0.x,a0.y,a0.z,a0.w,a1.x,a1.y,a1.z,a1.w};
            float bv[4] = {bb.x,bb.y,bb.z,bb.w};
            #pragma unroll
            for (int i2 = 0; i2 < 8; ++i2)
                #pragma unroll
                for (int j2 = 0; j2 < 4; ++j2) acc[i2][j2] += av[i2]*bv[j2];
        }
        __syncthreads();
    }
    #pragma unroll
    for (int i2 = 0; i2 < 8; ++i2) {
        *(float4*)&g_u[(size_t)(r0+ty*8+i2)*Dd + d0 + tx*4] =
            make_float4(acc[i2][0], acc[i2][1], acc[i2][2], acc[i2][3]);
    }
}

// ------------------- K5: per-row dots, warp per row ------------------------
__global__ void dots_kernel() {
    int tid = threadIdx.x;
    int w = tid >> 5, lane = tid & 31;
    int r = blockIdx.x * 8 + w;
    int i = r & (Ss-1);
    const float* xr = g_x + (size_t)r*Dd;
    float dp = 0.f, dm = 0.f, a1 = 0.f, a2 = 0.f;
    #pragma unroll
    for (int s = 0; s < 2; ++s) {
        int c = s*128 + lane*4;
        float4 x  = *(const float4*)&xr[c];
        float4 c1 = *(const float4*)&g_c1[c];
        float4 c2 = *(const float4*)&g_c2[c];
        a1 += x.x*c1.x + x.y*c1.y + x.z*c1.z + x.w*c1.w;
        a2 += x.x*c2.x + x.y*c2.y + x.z*c2.z + x.w*c2.w;
        if (i < Ss-1) {
            float4 up = *(const float4*)&g_u[(size_t)(r+1)*Dd + c];
            dp += x.x*up.x + x.y*up.y + x.z*up.z + x.w*up.w;
        }
        if (i > 0) {
            float4 um = *(const float4*)&g_u[(size_t)(r-1)*Dd + c];
            dm += x.x*um.x + x.y*um.y + x.z*um.z + x.w*um.w;
        }
    }
    #pragma unroll
    for (int o = 16; o; o >>= 1) {
        dp += __shfl_xor_sync(0xffffffffu, dp, o);
        dm += __shfl_xor_sync(0xffffffffu, dm, o);
        a1 += __shfl_xor_sync(0xffffffffu, a1, o);
        a2 += __shfl_xor_sync(0xffffffffu, a2, o);
    }
    if (lane == 0) { g_dotp[r] = dp; g_dotm[r] = dm; g_A1[r] = a1; g_A2[r] = a2; }
}

// ------------------- K6: probs + l + diag (fused) --------------------------
__device__ __forceinline__ void probs(const int* __restrict__ ebase, int i, int r,
                                      float& pp, float& pm, float& ps) {
    bool ap = (i < Ss-1) && (ebase[(size_t)i*Ss + i + 1] != 0);
    bool am = (i > 0)    && (ebase[(size_t)i*Ss + i - 1] != 0);
    if (!ap && !am) { pp = pm = ps = 1.0f/(float)Ss; return; }
    ps = 0.f;
    if (ap && am) {
        float c0 = g_c0;
        float sp = (g_dotp[r] + g_A1[r] + g_A2[r+1] + c0) * (1.0f/256.0f);
        float sm = (g_dotm[r] + g_A1[r] + g_A2[r-1] + c0) * (1.0f/256.0f);
        float m = fmaxf(sp, sm);
        float ep = expf(sp - m), em = expf(sm - m);
        float inv = 1.0f/(ep + em);
        pp = ep*inv; pm = em*inv;
    } else if (ap) { pp = 1.f; pm = 0.f; }
    else           { pp = 0.f; pm = 1.f; }
}

__global__ void probldiag_kernel(const int* __restrict__ eos,
                                 const float* __restrict__ prior) {
    int r = blockIdx.x*256 + threadIdx.x;
    if (r >= Rr) return;
    int b = r >> 11, i = r & (Ss-1);
    const int* ebase = eos + (size_t)b*Ss*Ss;
    const float* pbase = prior + (size_t)b*Ss*Ss;

    float pp_r, pm_r, ps_r;
    probs(ebase, i, r, pp_r, pm_r, ps_r);

    if (i < Ss-1) {
        float pp2, pm2, ps2;
        probs(ebase, i+1, r+1, pp2, pm2, ps2);
        float n1 = sqrtf(pp_r*pm2 + 1e-9f);
        float pr = pbase[(size_t)i*Ss + i + 1];
        float nb = pr + (1.0f - pr)*n1;
        g_l[r] = log((double)nb + 1e-9);
    } else {
        g_l[r] = 0.0;
    }
    float nd = sqrtf(ps_r*ps_r + 1e-9f);
    float pr = pbase[(size_t)i*Ss + i];
    g_diag[r] = pr + (1.0f - pr)*nd;
}

// ------------------- K7: per-batch exclusive prefix sum (f64) --------------
__global__ void scan_kernel() {
    __shared__ double ps[1024];
    int b = blockIdx.x, t = threadIdx.x;
    int base = b*Ss;
    double a0 = g_l[base + 2*t];
    double a1 = g_l[base + 2*t + 1];
    double s = a0 + a1;
    ps[t] = s;
    __syncthreads();
    for (int off = 1; off < 1024; off <<= 1) {
        double v = (t >= off) ? ps[t - off] : 0.0;
        __syncthreads();
        ps[t] += v;
        __syncthreads();
    }
    double excl = ps[t] - s;
    g_P[base + 2*t]     = excl;
    g_P[base + 2*t + 1] = excl + a0;
}

// ------------------- K8: band limits, 1 thread per row ---------------------
__global__ void band_kernel() {
    int r = blockIdx.x*1024 + threadIdx.x;
    int b = r >> 11, i = r & (Ss-1);
    const double* P = g_P + b*Ss;
    double Pi = P[i];
    const double T = 46.0;   // exp(-46) ~ 1e-20 << 1e-9 floor

    int lo2 = i, hi2 = Ss-1;
    while (lo2 < hi2) {
        int mid = (lo2 + hi2 + 1) >> 1;
        if (Pi - P[mid] <= T) lo2 = mid; else hi2 = mid - 1;
    }
    int a = 0, b2 = i;
    while (a < b2) {
        int mid = (a + b2) >> 1;
        if (P[mid] - Pi <= T) b2 = mid; else a = mid + 1;
    }
    g_lo[r] = a; g_hi[r] = lo2;
}

// ------------------- K9: banded output, 4 rows/block, float4 ---------------
__global__ void out_kernel(float* __restrict__ out) {
    int r0 = blockIdx.x * 4;
    #pragma unroll
    for (int rr = 0; rr < 4; ++rr) {
        int r = r0 + rr;
        int b = r >> 11, i = r & (Ss-1);
        const double* P = g_P + b*Ss;
        double Pi = P[i];
        int lo = g_lo[r], hi = g_hi[r];
        float dg = g_diag[r];
        float* orow = out + (size_t)r*Ss;
        #pragma unroll
        for (int s = 0; s < 2; ++s) {
            int t = threadIdx.x + s*256;
            int j0 = t*4;
            float4 o;
            if (j0 + 3 < lo || j0 > hi) {
                o = make_float4(1e-9f, 1e-9f, 1e-9f, 1e-9f);
            } else {
                float v[4];
                #pragma unroll
                for (int q = 0; q < 4; ++q) {
                    int j = j0 + q;
                    float x;
                    if (j < lo || j > hi) x = 1e-9f;
                    else if (j == i)      x = dg;
                    else {
                        double e = (j > i) ? (P[j] - Pi) : (Pi - P[j]);
                        x = expf((float)e) + 1e-9f;
                    }
                    v[q] = x;
                }
                o = make_float4(v[0], v[1], v[2], v[3]);
            }
            *(float4*)&orow[j0] = o;
        }
    }
}

// ------------------- launch -------------------------------------------------
extern "C" void kernel_launch(void* const* d_in, const int* in_sizes, int n_in,
                              void* d_out, int out_size) {
    const float* ctx   = (const float*)d_in[0];
    const float* prior = (const float*)d_in[1];
    const float* Wq    = (const float*)d_in[2];
    const float* bq    = (const float*)d_in[3];
    const float* Wk    = (const float*)d_in[4];
    const float* bk    = (const float*)d_in[5];
    const float* la    = (const float*)d_in[6];
    const float* lb    = (const float*)d_in[7];
    const int*   eos   = (const int*)d_in[8];
    float* out = (float*)d_out;

    ln_kernel<<<Rr/8, 256>>>(ctx, la, lb);
    bias_kernel<<<1, 256>>>(Wq, Wk, bq, bk);
    m_kernel<<<dim3(16,16), dim3(16,16)>>>(Wq, Wk);
    gemm_kernel<<<dim3(Dd/64, Rr/128), 256>>>();
    dots_kernel<<<Rr/8, 256>>>();
    probldiag_kernel<<<Rr/256, 256>>>(eos, prior);
    scan_kernel<<<Bb, 1024>>>();
    band_kernel<<<Rr/1024, 1024>>>();
    out_kernel<<<Rr/4, 256>>>(out);
}

// round 7
// speedup vs baseline: 2.2700x; 1.0623x over previous
#include <cuda_runtime.h>
#include <math.h>

#define Bb 4
#define Ss 2048
#define Dd 256
#define Rr (Bb*Ss)

// ------------------- scratch (device globals; no allocation) ---------------
__device__ __align__(16) float g_x[Rr*Dd];   // normalized context
__device__ __align__(16) float g_u[Rr*Dd];   // U[r] = M x_r
__device__ __align__(16) float g_M[Dd*Dd];   // M = Wq^T Wk
__device__ __align__(16) float g_c1[Dd], g_c2[Dd];
__device__ float g_c0;
__device__ float g_dotp[Rr], g_dotm[Rr], g_A1[Rr], g_A2[Rr];
__device__ float g_diag[Rr];
__device__ double g_P[Rr];
__device__ int g_lo[Rr], g_hi[Rr];

// ------------------- K1: prologue = LN (1024 blocks) + M (256) + bias (1) --
__global__ void prologue_kernel(const float* __restrict__ ctx,
                                const float* __restrict__ la,
                                const float* __restrict__ lb,
                                const float* __restrict__ Wq,
                                const float* __restrict__ Wk,
                                const float* __restrict__ bq,
                                const float* __restrict__ bk) {
    int bid = blockIdx.x;
    int t = threadIdx.x;
    if (bid < 1024) {
        // ---- LayerNorm: warp per row, 8 rows/block ----
        int w = t >> 5, lane = t & 31;
        int r = bid * 8 + w;
        const float* src = ctx + (size_t)r * Dd;
        float4 v0 = *(const float4*)&src[lane*4];
        float4 v1 = *(const float4*)&src[128 + lane*4];
        float s = v0.x+v0.y+v0.z+v0.w + v1.x+v1.y+v1.z+v1.w;
        #pragma unroll
        for (int o = 16; o; o >>= 1) s += __shfl_xor_sync(0xffffffffu, s, o);
        float mean = s * (1.0f/Dd);
        float d0x=v0.x-mean, d0y=v0.y-mean, d0z=v0.z-mean, d0w=v0.w-mean;
        float d1x=v1.x-mean, d1y=v1.y-mean, d1z=v1.z-mean, d1w=v1.w-mean;
        float sq = d0x*d0x+d0y*d0y+d0z*d0z+d0w*d0w + d1x*d1x+d1y*d1y+d1z*d1z+d1w*d1w;
        #pragma unroll
        for (int o = 16; o; o >>= 1) sq += __shfl_xor_sync(0xffffffffu, sq, o);
        float inv = 1.0f / (sqrtf(sq * (1.0f/(Dd-1))) + 1e-6f);
        float4 a0 = *(const float4*)&la[lane*4];
        float4 a1 = *(const float4*)&la[128 + lane*4];
        float4 b0 = *(const float4*)&lb[lane*4];
        float4 b1 = *(const float4*)&lb[128 + lane*4];
        float* dst = g_x + (size_t)r * Dd;
        *(float4*)&dst[lane*4] = make_float4(a0.x*d0x*inv + b0.x, a0.y*d0y*inv + b0.y,
                                             a0.z*d0z*inv + b0.z, a0.w*d0w*inv + b0.w);
        *(float4*)&dst[128 + lane*4] = make_float4(a1.x*d1x*inv + b1.x, a1.y*d1y*inv + b1.y,
                                                   a1.z*d1z*inv + b1.z, a1.w*d1w*inv + b1.w);
    } else if (bid < 1280) {
        // ---- M[d,e] = sum_f Wq[f,d] Wk[f,e] ----
        __shared__ float sq[16][17], sk[16][17];
        int mb = bid - 1024;
        int bx = mb & 15, by = mb >> 4;
        int tx = t & 15, ty = t >> 4;
        int d = by*16 + ty;
        int e = bx*16 + tx;
        float acc = 0.f;
        for (int f0 = 0; f0 < Dd; f0 += 16) {
            sq[ty][tx] = Wq[(f0+ty)*Dd + by*16 + tx];
            sk[ty][tx] = Wk[(f0+ty)*Dd + bx*16 + tx];
            __syncthreads();
            #pragma unroll
            for (int f = 0; f < 16; ++f) acc += sq[f][ty] * sk[f][tx];
            __syncthreads();
        }
        g_M[d*Dd + e] = acc;
    } else {
        // ---- c1 = Wq^T bk, c2 = Wk^T bq, c0 = bq.bk ----
        __shared__ float red[256];
        float a1 = 0.f, a2 = 0.f;
        for (int f = 0; f < Dd; ++f) {
            a1 += Wq[f*Dd + t] * bk[f];
            a2 += Wk[f*Dd + t] * bq[f];
        }
        g_c1[t] = a1; g_c2[t] = a2;
        red[t] = bq[t] * bk[t];
        __syncthreads();
        for (int s = 128; s; s >>= 1) { if (t < s) red[t] += red[t+s]; __syncthreads(); }
        if (t == 0) g_c0 = red[0];
    }
}

// ------------------- K2: U = X @ M^T, 128x128 tile, 8x8 micro (split 64) ---
__global__ void __launch_bounds__(256) gemm_kernel() {
    __shared__ __align__(16) float As[16][132];
    __shared__ __align__(16) float Bs[16][132];
    int tid = threadIdx.x;
    int tx = tid & 15;     // col group
    int ty = tid >> 4;     // row group
    int d0 = blockIdx.x * 128;
    int r0 = blockIdx.y * 128;

    float acc[8][8] = {};
    float4 pa[2], pb[2];

    // prefetch first k-tile
    #pragma unroll
    for (int s = 0; s < 2; ++s) {
        int idx = tid + s*256;
        int row = idx >> 2, seg = idx & 3;
        pa[s] = *(const float4*)&g_x[(size_t)(r0+row)*Dd + seg*4];
        pb[s] = *(const float4*)&g_M[(size_t)(d0+row)*Dd + seg*4];
    }

    for (int e0 = 0; e0 < Dd; e0 += 16) {
        // scatter prefetched tile into transposed smem
        #pragma unroll
        for (int s = 0; s < 2; ++s) {
            int idx = tid + s*256;
            int row = idx >> 2, seg = (idx & 3) * 4;
            As[seg+0][row] = pa[s].x; As[seg+1][row] = pa[s].y;
            As[seg+2][row] = pa[s].z; As[seg+3][row] = pa[s].w;
            Bs[seg+0][row] = pb[s].x; Bs[seg+1][row] = pb[s].y;
            Bs[seg+2][row] = pb[s].z; Bs[seg+3][row] = pb[s].w;
        }
        __syncthreads();
        if (e0 + 16 < Dd) {
            #pragma unroll
            for (int s = 0; s < 2; ++s) {
                int idx = tid + s*256;
                int row = idx >> 2, seg = idx & 3;
                pa[s] = *(const float4*)&g_x[(size_t)(r0+row)*Dd + e0 + 16 + seg*4];
                pb[s] = *(const float4*)&g_M[(size_t)(d0+row)*Dd + e0 + 16 + seg*4];
            }
        }
        #pragma unroll
        for (int k = 0; k < 16; ++k) {
            float4 a0 = *(const float4*)&As[k][ty*4];
            float4 a1 = *(const float4*)&As[k][ty*4 + 64];
            float4 b0 = *(const float4*)&Bs[k][tx*4];
            float4 b1 = *(const float4*)&Bs[k][tx*4 + 64];
            float av[8] = {a0.x,a0.y,a0.z,a0.w, a1.x,a1.y,a1.z,a1.w};
            float bv[8] = {b0.x,b0.y,b0.z,b0.w, b1.x,b1.y,b1.z,b1.w};
            #pragma unroll
            for (int i2 = 0; i2 < 8; ++i2)
                #pragma unroll
                for (int j2 = 0; j2 < 8; ++j2) acc[i2][j2] += av[i2]*bv[j2];
        }
        __syncthreads();
    }
    #pragma unroll
    for (int ri = 0; ri < 2; ++ri) {
        #pragma unroll
        for (int i2 = 0; i2 < 4; ++i2) {
            int row = r0 + ri*64 + ty*4 + i2;
            float* orow = g_u + (size_t)row*Dd + d0;
            *(float4*)&orow[tx*4] = make_float4(acc[ri*4+i2][0], acc[ri*4+i2][1],
                                                acc[ri*4+i2][2], acc[ri*4+i2][3]);
            *(float4*)&orow[64 + tx*4] = make_float4(acc[ri*4+i2][4], acc[ri*4+i2][5],
                                                     acc[ri*4+i2][6], acc[ri*4+i2][7]);
        }
    }
}

// ------------------- K3: per-row dots, warp per row ------------------------
__global__ void dots_kernel() {
    int tid = threadIdx.x;
    int w = tid >> 5, lane = tid & 31;
    int r = blockIdx.x * 8 + w;
    int i = r & (Ss-1);
    const float* xr = g_x + (size_t)r*Dd;
    float dp = 0.f, dm = 0.f, a1 = 0.f, a2 = 0.f;
    #pragma unroll
    for (int s = 0; s < 2; ++s) {
        int c = s*128 + lane*4;
        float4 x  = *(const float4*)&xr[c];
        float4 c1 = *(const float4*)&g_c1[c];
        float4 c2 = *(const float4*)&g_c2[c];
        a1 += x.x*c1.x + x.y*c1.y + x.z*c1.z + x.w*c1.w;
        a2 += x.x*c2.x + x.y*c2.y + x.z*c2.z + x.w*c2.w;
        if (i < Ss-1) {
            float4 up = *(const float4*)&g_u[(size_t)(r+1)*Dd + c];
            dp += x.x*up.x + x.y*up.y + x.z*up.z + x.w*up.w;
        }
        if (i > 0) {
            float4 um = *(const float4*)&g_u[(size_t)(r-1)*Dd + c];
            dm += x.x*um.x + x.y*um.y + x.z*um.z + x.w*um.w;
        }
    }
    #pragma unroll
    for (int o = 16; o; o >>= 1) {
        dp += __shfl_xor_sync(0xffffffffu, dp, o);
        dm += __shfl_xor_sync(0xffffffffu, dm, o);
        a1 += __shfl_xor_sync(0xffffffffu, a1, o);
        a2 += __shfl_xor_sync(0xffffffffu, a2, o);
    }
    if (lane == 0) { g_dotp[r] = dp; g_dotm[r] = dm; g_A1[r] = a1; g_A2[r] = a2; }
}

// ------------------- probs helper ------------------------------------------
__device__ __forceinline__ void probs(const int* __restrict__ ebase, int i, int r,
                                      float& pp, float& pm, float& ps) {
    bool ap = (i < Ss-1) && (ebase[(size_t)i*Ss + i + 1] != 0);
    bool am = (i > 0)    && (ebase[(size_t)i*Ss + i - 1] != 0);
    if (!ap && !am) { pp = pm = ps = 1.0f/(float)Ss; return; }
    ps = 0.f;
    if (ap && am) {
        float c0 = g_c0;
        float sp = (g_dotp[r] + g_A1[r] + g_A2[r+1] + c0) * (1.0f/256.0f);
        float sm = (g_dotm[r] + g_A1[r] + g_A2[r-1] + c0) * (1.0f/256.0f);
        float m = fmaxf(sp, sm);
        float ep = expf(sp - m), em = expf(sm - m);
        float inv = 1.0f/(ep + em);
        pp = ep*inv; pm = em*inv;
    } else if (ap) { pp = 1.f; pm = 0.f; }
    else           { pp = 0.f; pm = 1.f; }
}

// ------------------- K4: fused probs + log + scan + band + diag ------------
// grid = Bb blocks of 1024 threads; each thread owns rows 2t, 2t+1 of batch b.
__global__ void scanfuse_kernel(const int* __restrict__ eos,
                                const float* __restrict__ prior) {
    __shared__ double ps[1024];
    __shared__ double Ps[Ss];
    int b = blockIdx.x, t = threadIdx.x;
    int base = b*Ss;
    const int* ebase = eos + (size_t)b*Ss*Ss;
    const float* pbase = prior + (size_t)b*Ss*Ss;

    int i0 = 2*t, i1 = 2*t + 1;
    float pp0, pm0, ps0, pp1, pm1, ps1;
    probs(ebase, i0, base+i0, pp0, pm0, ps0);
    probs(ebase, i1, base+i1, pp1, pm1, ps1);

    // l for row i0 (uses pm of row i0+1 = i1)
    double l0;
    {
        float n1 = sqrtf(pp0*pm1 + 1e-9f);
        float pr = pbase[(size_t)i0*Ss + i0 + 1];
        float nb = pr + (1.0f - pr)*n1;
        l0 = log((double)nb + 1e-9);
    }
    // l for row i1 (uses pm of row i1+1)
    double l1 = 0.0;
    if (i1 < Ss-1) {
        float pp2, pm2, ps2;
        probs(ebase, i1+1, base+i1+1, pp2, pm2, ps2);
        float n1 = sqrtf(pp1*pm2 + 1e-9f);
        float pr = pbase[(size_t)i1*Ss + i1 + 1];
        float nb = pr + (1.0f - pr)*n1;
        l1 = log((double)nb + 1e-9);
    }
    // diagonal values
    {
        float nd0 = sqrtf(ps0*ps0 + 1e-9f);
        float pr0 = pbase[(size_t)i0*Ss + i0];
        g_diag[base+i0] = pr0 + (1.0f - pr0)*nd0;
        float nd1 = sqrtf(ps1*ps1 + 1e-9f);
        float pr1 = pbase[(size_t)i1*Ss + i1];
        g_diag[base+i1] = pr1 + (1.0f - pr1)*nd1;
    }

    // inclusive scan over pair sums
    double s = l0 + l1;
    ps[t] = s;
    __syncthreads();
    for (int off = 1; off < 1024; off <<= 1) {
        double v = (t >= off) ? ps[t - off] : 0.0;
        __syncthreads();
        ps[t] += v;
        __syncthreads();
    }
    double excl = ps[t] - s;
    Ps[i0] = excl;
    Ps[i1] = excl + l0;
    g_P[base+i0] = excl;
    g_P[base+i1] = excl + l0;
    __syncthreads();

    // band search in smem for both rows
    const double T = 46.0;   // exp(-46) ~ 1e-20 << 1e-9 floor
    #pragma unroll
    for (int q = 0; q < 2; ++q) {
        int i = 2*t + q;
        double Pi = Ps[i];
        int lo2 = i, hi2 = Ss-1;
        while (lo2 < hi2) {
            int mid = (lo2 + hi2 + 1) >> 1;
            if (Pi - Ps[mid] <= T) lo2 = mid; else hi2 = mid - 1;
        }
        int a = 0, b2 = i;
        while (a < b2) {
            int mid = (a + b2) >> 1;
            if (Ps[mid] - Pi <= T) b2 = mid; else a = mid + 1;
        }
        g_lo[base+i] = a; g_hi[base+i] = lo2;
    }
}

// ------------------- K5: banded output, 4 rows/block, float4 ---------------
__global__ void out_kernel(float* __restrict__ out) {
    int r0 = blockIdx.x * 4;
    #pragma unroll
    for (int rr = 0; rr < 4; ++rr) {
        int r = r0 + rr;
        int b = r >> 11, i = r & (Ss-1);
        const double* P = g_P + b*Ss;
        double Pi = P[i];
        int lo = g_lo[r], hi = g_hi[r];
        float dg = g_diag[r];
        float* orow = out + (size_t)r*Ss;
        #pragma unroll
        for (int s = 0; s < 2; ++s) {
            int t = threadIdx.x + s*256;
            int j0 = t*4;
            float4 o;
            if (j0 + 3 < lo || j0 > hi) {
                o = make_float4(1e-9f, 1e-9f, 1e-9f, 1e-9f);
            } else {
                float v[4];
                #pragma unroll
                for (int q = 0; q < 4; ++q) {
                    int j = j0 + q;
                    float x;
                    if (j < lo || j > hi) x = 1e-9f;
                    else if (j == i)      x = dg;
                    else {
                        double e = (j > i) ? (P[j] - Pi) : (Pi - P[j]);
                        x = expf((float)e) + 1e-9f;
                    }
                    v[q] = x;
                }
                o = make_float4(v[0], v[1], v[2], v[3]);
            }
            *(float4*)&orow[j0] = o;
        }
    }
}

// ------------------- launch -------------------------------------------------
extern "C" void kernel_launch(void* const* d_in, const int* in_sizes, int n_in,
                              void* d_out, int out_size) {
    const float* ctx   = (const float*)d_in[0];
    const float* prior = (const float*)d_in[1];
    const float* Wq    = (const float*)d_in[2];
    const float* bq    = (const float*)d_in[3];
    const float* Wk    = (const float*)d_in[4];
    const float* bk    = (const float*)d_in[5];
    const float* la    = (const float*)d_in[6];
    const float* lb    = (const float*)d_in[7];
    const int*   eos   = (const int*)d_in[8];
    float* out = (float*)d_out;

    prologue_kernel<<<1281, 256>>>(ctx, la, lb, Wq, Wk, bq, bk);
    gemm_kernel<<<dim3(Dd/128, Rr/128), 256>>>();
    dots_kernel<<<Rr/8, 256>>>();
    scanfuse_kernel<<<Bb, 1024>>>(eos, prior);
    out_kernel<<<Rr/4, 256>>>(out);
}

// round 8
// speedup vs baseline: 2.6911x; 1.1855x over previous
#include <cuda_runtime.h>
#include <math.h>

#define Bb 4
#define Ss 2048
#define Dd 256
#define Rr (Bb*Ss)

// ------------------- scratch (device globals; no allocation) ---------------
__device__ __align__(16) float g_u[Rr*Dd];   // U[r] = M x_r
__device__ __align__(16) float g_M[Dd*Dd];   // M = Wq^T Wk
__device__ __align__(16) float g_c1[Dd], g_c2[Dd];
__device__ float g_c0;
__device__ float g_mean[Rr], g_inv[Rr];      // LN stats
__device__ float g_dotp[Rr], g_dotm[Rr], g_A1[Rr], g_A2[Rr];
__device__ float g_diag[Rr];
__device__ double g_l[Rr], g_P[Rr];
__device__ int g_lo[Rr], g_hi[Rr];

// ------------------- K1: prologue = LN stats (1024) + M (256) + bias (1) ---
__global__ void prologue_kernel(const float* __restrict__ ctx,
                                const float* __restrict__ Wq,
                                const float* __restrict__ Wk,
                                const float* __restrict__ bq,
                                const float* __restrict__ bk) {
    int bid = blockIdx.x;
    int t = threadIdx.x;
    if (bid < 1024) {
        // ---- LN stats only: warp per row, 8 rows/block ----
        int w = t >> 5, lane = t & 31;
        int r = bid * 8 + w;
        const float* src = ctx + (size_t)r * Dd;
        float4 v0 = *(const float4*)&src[lane*4];
        float4 v1 = *(const float4*)&src[128 + lane*4];
        float s = v0.x+v0.y+v0.z+v0.w + v1.x+v1.y+v1.z+v1.w;
        #pragma unroll
        for (int o = 16; o; o >>= 1) s += __shfl_xor_sync(0xffffffffu, s, o);
        float mean = s * (1.0f/Dd);
        float d0x=v0.x-mean, d0y=v0.y-mean, d0z=v0.z-mean, d0w=v0.w-mean;
        float d1x=v1.x-mean, d1y=v1.y-mean, d1z=v1.z-mean, d1w=v1.w-mean;
        float sq = d0x*d0x+d0y*d0y+d0z*d0z+d0w*d0w + d1x*d1x+d1y*d1y+d1z*d1z+d1w*d1w;
        #pragma unroll
        for (int o = 16; o; o >>= 1) sq += __shfl_xor_sync(0xffffffffu, sq, o);
        if (lane == 0) {
            g_mean[r] = mean;
            g_inv[r] = 1.0f / (sqrtf(sq * (1.0f/(Dd-1))) + 1e-6f);
        }
    } else if (bid < 1280) {
        // ---- M[d,e] = sum_f Wq[f,d] Wk[f,e] ----
        __shared__ float sq[16][17], sk[16][17];
        int mb = bid - 1024;
        int bx = mb & 15, by = mb >> 4;
        int tx = t & 15, ty = t >> 4;
        float acc = 0.f;
        for (int f0 = 0; f0 < Dd; f0 += 16) {
            sq[ty][tx] = Wq[(f0+ty)*Dd + by*16 + tx];
            sk[ty][tx] = Wk[(f0+ty)*Dd + bx*16 + tx];
            __syncthreads();
            #pragma unroll
            for (int f = 0; f < 16; ++f) acc += sq[f][ty] * sk[f][tx];
            __syncthreads();
        }
        g_M[(by*16+ty)*Dd + bx*16 + tx] = acc;
    } else {
        // ---- c1 = Wq^T bk, c2 = Wk^T bq, c0 = bq.bk ----
        __shared__ float red[256];
        float a1 = 0.f, a2 = 0.f;
        for (int f = 0; f < Dd; ++f) {
            a1 += Wq[f*Dd + t] * bk[f];
            a2 += Wk[f*Dd + t] * bq[f];
        }
        g_c1[t] = a1; g_c2[t] = a2;
        red[t] = bq[t] * bk[t];
        __syncthreads();
        for (int s = 128; s; s >>= 1) { if (t < s) red[t] += red[t+s]; __syncthreads(); }
        if (t == 0) g_c0 = red[0];
    }
}

// ------------------- K2: U = X @ M^T with on-the-fly LN --------------------
__global__ void __launch_bounds__(256) gemm_kernel(const float* __restrict__ ctx,
                                                   const float* __restrict__ la,
                                                   const float* __restrict__ lb) {
    __shared__ __align__(16) float As[16][132];
    __shared__ __align__(16) float Bs[16][132];
    int tid = threadIdx.x;
    int tx = tid & 15;
    int ty = tid >> 4;
    int d0 = blockIdx.x * 128;
    int r0 = blockIdx.y * 128;

    // rows this thread loads (fixed across k-tiles)
    int rowL[2], segL[2];
    float mnL[2], ivL[2];
    #pragma unroll
    for (int s = 0; s < 2; ++s) {
        int idx = tid + s*256;
        rowL[s] = idx >> 2; segL[s] = (idx & 3) * 4;
        mnL[s] = g_mean[r0 + rowL[s]];
        ivL[s] = g_inv[r0 + rowL[s]];
    }

    float acc[8][8] = {};
    float4 pa[2], pb[2];

    // prefetch first k-tile (normalized A)
    #pragma unroll
    for (int s = 0; s < 2; ++s) {
        float4 v  = *(const float4*)&ctx[(size_t)(r0+rowL[s])*Dd + segL[s]];
        float4 l4 = *(const float4*)&la[segL[s]];
        float4 b4 = *(const float4*)&lb[segL[s]];
        float ax = l4.x*ivL[s], ay = l4.y*ivL[s], az = l4.z*ivL[s], aw = l4.w*ivL[s];
        pa[s] = make_float4(ax*(v.x-mnL[s])+b4.x, ay*(v.y-mnL[s])+b4.y,
                            az*(v.z-mnL[s])+b4.z, aw*(v.w-mnL[s])+b4.w);
        pb[s] = *(const float4*)&g_M[(size_t)(d0+rowL[s])*Dd + segL[s]];
    }

    for (int e0 = 0; e0 < Dd; e0 += 16) {
        #pragma unroll
        for (int s = 0; s < 2; ++s) {
            int row = rowL[s], seg = segL[s];
            As[seg+0][row] = pa[s].x; As[seg+1][row] = pa[s].y;
            As[seg+2][row] = pa[s].z; As[seg+3][row] = pa[s].w;
            Bs[seg+0][row] = pb[s].x; Bs[seg+1][row] = pb[s].y;
            Bs[seg+2][row] = pb[s].z; Bs[seg+3][row] = pb[s].w;
        }
        __syncthreads();
        if (e0 + 16 < Dd) {
            #pragma unroll
            for (int s = 0; s < 2; ++s) {
                int e = e0 + 16 + segL[s];
                float4 v  = *(const float4*)&ctx[(size_t)(r0+rowL[s])*Dd + e];
                float4 l4 = *(const float4*)&la[e];
                float4 b4 = *(const float4*)&lb[e];
                float ax = l4.x*ivL[s], ay = l4.y*ivL[s], az = l4.z*ivL[s], aw = l4.w*ivL[s];
                pa[s] = make_float4(ax*(v.x-mnL[s])+b4.x, ay*(v.y-mnL[s])+b4.y,
                                    az*(v.z-mnL[s])+b4.z, aw*(v.w-mnL[s])+b4.w);
                pb[s] = *(const float4*)&g_M[(size_t)(d0+rowL[s])*Dd + e];
            }
        }
        #pragma unroll
        for (int k = 0; k < 16; ++k) {
            float4 a0 = *(const float4*)&As[k][ty*4];
            float4 a1 = *(const float4*)&As[k][ty*4 + 64];
            float4 b0 = *(const float4*)&Bs[k][tx*4];
            float4 b1 = *(const float4*)&Bs[k][tx*4 + 64];
            float av[8] = {a0.x,a0.y,a0.z,a0.w, a1.x,a1.y,a1.z,a1.w};
            float bv[8] = {b0.x,b0.y,b0.z,b0.w, b1.x,b1.y,b1.z,b1.w};
            #pragma unroll
            for (int i2 = 0; i2 < 8; ++i2)
                #pragma unroll
                for (int j2 = 0; j2 < 8; ++j2) acc[i2][j2] += av[i2]*bv[j2];
        }
        __syncthreads();
    }
    #pragma unroll
    for (int ri = 0; ri < 2; ++ri) {
        #pragma unroll
        for (int i2 = 0; i2 < 4; ++i2) {
            int row = r0 + ri*64 + ty*4 + i2;
            float* orow = g_u + (size_t)row*Dd + d0;
            *(float4*)&orow[tx*4] = make_float4(acc[ri*4+i2][0], acc[ri*4+i2][1],
                                                acc[ri*4+i2][2], acc[ri*4+i2][3]);
            *(float4*)&orow[64 + tx*4] = make_float4(acc[ri*4+i2][4], acc[ri*4+i2][5],
                                                     acc[ri*4+i2][6], acc[ri*4+i2][7]);
        }
    }
}

// ------------------- K3: per-row dots, on-the-fly LN -----------------------
__global__ void dots_kernel(const float* __restrict__ ctx,
                            const float* __restrict__ la,
                            const float* __restrict__ lb) {
    int tid = threadIdx.x;
    int w = tid >> 5, lane = tid & 31;
    int r = blockIdx.x * 8 + w;
    int i = r & (Ss-1);
    float mean = g_mean[r], inv = g_inv[r];
    const float* cr = ctx + (size_t)r*Dd;
    float dp = 0.f, dm = 0.f, a1 = 0.f, a2 = 0.f;
    #pragma unroll
    for (int s = 0; s < 2; ++s) {
        int c = s*128 + lane*4;
        float4 v  = *(const float4*)&cr[c];
        float4 l4 = *(const float4*)&la[c];
        float4 b4 = *(const float4*)&lb[c];
        float4 x = make_float4(l4.x*inv*(v.x-mean)+b4.x, l4.y*inv*(v.y-mean)+b4.y,
                               l4.z*inv*(v.z-mean)+b4.z, l4.w*inv*(v.w-mean)+b4.w);
        float4 c1 = *(const float4*)&g_c1[c];
        float4 c2 = *(const float4*)&g_c2[c];
        a1 += x.x*c1.x + x.y*c1.y + x.z*c1.z + x.w*c1.w;
        a2 += x.x*c2.x + x.y*c2.y + x.z*c2.z + x.w*c2.w;
        if (i < Ss-1) {
            float4 up = *(const float4*)&g_u[(size_t)(r+1)*Dd + c];
            dp += x.x*up.x + x.y*up.y + x.z*up.z + x.w*up.w;
        }
        if (i > 0) {
            float4 um = *(const float4*)&g_u[(size_t)(r-1)*Dd + c];
            dm += x.x*um.x + x.y*um.y + x.z*um.z + x.w*um.w;
        }
    }
    #pragma unroll
    for (int o = 16; o; o >>= 1) {
        dp += __shfl_xor_sync(0xffffffffu, dp, o);
        dm += __shfl_xor_sync(0xffffffffu, dm, o);
        a1 += __shfl_xor_sync(0xffffffffu, a1, o);
        a2 += __shfl_xor_sync(0xffffffffu, a2, o);
    }
    if (lane == 0) { g_dotp[r] = dp; g_dotm[r] = dm; g_A1[r] = a1; g_A2[r] = a2; }
}

// ------------------- probs helper ------------------------------------------
__device__ __forceinline__ void probs(const int* __restrict__ ebase, int i, int r,
                                      float& pp, float& pm, float& ps) {
    bool ap = (i < Ss-1) && (ebase[(size_t)i*Ss + i + 1] != 0);
    bool am = (i > 0)    && (ebase[(size_t)i*Ss + i - 1] != 0);
    if (!ap && !am) { pp = pm = ps = 1.0f/(float)Ss; return; }
    ps = 0.f;
    if (ap && am) {
        float c0 = g_c0;
        float sp = (g_dotp[r] + g_A1[r] + g_A2[r+1] + c0) * (1.0f/256.0f);
        float sm = (g_dotm[r] + g_A1[r] + g_A2[r-1] + c0) * (1.0f/256.0f);
        float m = fmaxf(sp, sm);
        float ep = expf(sp - m), em = expf(sm - m);
        float inv = 1.0f/(ep + em);
        pp = ep*inv; pm = em*inv;
    } else if (ap) { pp = 1.f; pm = 0.f; }
    else           { pp = 0.f; pm = 1.f; }
}

// ------------------- K4: wide probs + log + diag ---------------------------
__global__ void lprob_kernel(const int* __restrict__ eos,
                             const float* __restrict__ prior) {
    int r = blockIdx.x*256 + threadIdx.x;
    if (r >= Rr) return;
    int b = r >> 11, i = r & (Ss-1);
    const int* ebase = eos + (size_t)b*Ss*Ss;
    const float* pbase = prior + (size_t)b*Ss*Ss;

    float pp, pm, ps;
    probs(ebase, i, r, pp, pm, ps);

    if (i < Ss-1) {
        float pp2, pm2, ps2;
        probs(ebase, i+1, r+1, pp2, pm2, ps2);
        float n1 = sqrtf(pp*pm2 + 1e-9f);
        float pr = pbase[(size_t)i*Ss + i + 1];
        float nb = pr + (1.0f - pr)*n1;
        g_l[r] = log((double)nb + 1e-9);
    } else {
        g_l[r] = 0.0;
    }
    float nd = sqrtf(ps*ps + 1e-9f);
    float pr = pbase[(size_t)i*Ss + i];
    g_diag[r] = pr + (1.0f - pr)*nd;
}

// ------------------- K5: shuffle-based exclusive scan (f64) ----------------
__global__ void scan_kernel() {
    __shared__ double wsum[32];
    int b = blockIdx.x, t = threadIdx.x;
    int lane = t & 31, w = t >> 5;
    int base = b*Ss;
    double l0 = g_l[base + 2*t];
    double l1 = g_l[base + 2*t + 1];
    double s = l0 + l1;
    // inclusive warp scan of pair sums
    double v = s;
    #pragma unroll
    for (int o = 1; o < 32; o <<= 1) {
        double n = __shfl_up_sync(0xffffffffu, v, o);
        if (lane >= o) v += n;
    }
    if (lane == 31) wsum[w] = v;
    __syncthreads();
    if (w == 0) {
        double x = wsum[lane];
        #pragma unroll
        for (int o = 1; o < 32; o <<= 1) {
            double n = __shfl_up_sync(0xffffffffu, x, o);
            if (lane >= o) x += n;
        }
        wsum[lane] = x;
    }
    __syncthreads();
    double off = (w > 0) ? wsum[w-1] : 0.0;
    double excl = off + v - s;
    g_P[base + 2*t]     = excl;
    g_P[base + 2*t + 1] = excl + l0;
}

// ------------------- K6: wide band search (P in L2) ------------------------
__global__ void band_kernel() {
    int r = blockIdx.x*1024 + threadIdx.x;
    int b = r >> 11, i = r & (Ss-1);
    const double* P = g_P + b*Ss;
    double Pi = P[i];
    const double T = 46.0;   // exp(-46) ~ 1e-20 << 1e-9 floor

    int lo2 = i, hi2 = Ss-1;
    while (lo2 < hi2) {
        int mid = (lo2 + hi2 + 1) >> 1;
        if (Pi - P[mid] <= T) lo2 = mid; else hi2 = mid - 1;
    }
    int a = 0, b2 = i;
    while (a < b2) {
        int mid = (a + b2) >> 1;
        if (P[mid] - Pi <= T) b2 = mid; else a = mid + 1;
    }
    g_lo[r] = a; g_hi[r] = lo2;
}

// ------------------- K7: banded output, 4 rows/block, float4 ---------------
__global__ void out_kernel(float* __restrict__ out) {
    int r0 = blockIdx.x * 4;
    #pragma unroll
    for (int rr = 0; rr < 4; ++rr) {
        int r = r0 + rr;
        int b = r >> 11, i = r & (Ss-1);
        const double* P = g_P + b*Ss;
        double Pi = P[i];
        int lo = g_lo[r], hi = g_hi[r];
        float dg = g_diag[r];
        float* orow = out + (size_t)r*Ss;
        #pragma unroll
        for (int s = 0; s < 2; ++s) {
            int t = threadIdx.x + s*256;
            int j0 = t*4;
            float4 o;
            if (j0 + 3 < lo || j0 > hi) {
                o = make_float4(1e-9f, 1e-9f, 1e-9f, 1e-9f);
            } else {
                float v[4];
                #pragma unroll
                for (int q = 0; q < 4; ++q) {
                    int j = j0 + q;
                    float x;
                    if (j < lo || j > hi) x = 1e-9f;
                    else if (j == i)      x = dg;
                    else {
                        double e = (j > i) ? (P[j] - Pi) : (Pi - P[j]);
                        x = expf((float)e) + 1e-9f;
                    }
                    v[q] = x;
                }
                o = make_float4(v[0], v[1], v[2], v[3]);
            }
            *(float4*)&orow[j0] = o;
        }
    }
}

// ------------------- launch -------------------------------------------------
extern "C" void kernel_launch(void* const* d_in, const int* in_sizes, int n_in,
                              void* d_out, int out_size) {
    const float* ctx   = (const float*)d_in[0];
    const float* prior = (const float*)d_in[1];
    const float* Wq    = (const float*)d_in[2];
    const float* bq    = (const float*)d_in[3];
    const float* Wk    = (const float*)d_in[4];
    const float* bk    = (const float*)d_in[5];
    const float* la    = (const float*)d_in[6];
    const float* lb    = (const float*)d_in[7];
    const int*   eos   = (const int*)d_in[8];
    float* out = (float*)d_out;

    prologue_kernel<<<1281, 256>>>(ctx, Wq, Wk, bq, bk);
    gemm_kernel<<<dim3(Dd/128, Rr/128), 256>>>(ctx, la, lb);
    dots_kernel<<<Rr/8, 256>>>(ctx, la, lb);
    lprob_kernel<<<Rr/256, 256>>>(eos, prior);
    scan_kernel<<<Bb, 1024>>>();
    band_kernel<<<Rr/1024, 1024>>>();
    out_kernel<<<Rr/4, 256>>>(out);
}

// round 11
// speedup vs baseline: 2.8307x; 1.0519x over previous
#include <cuda_runtime.h>
#include <math.h>

#define Bb 4
#define Ss 2048
#define Dd 256
#define Rr (Bb*Ss)

// ------------------- scratch (device globals; no allocation) ---------------
__device__ __align__(16) float g_M[Dd*Dd];   // M = Wq^T Wk
__device__ __align__(16) float g_c1[Dd], g_c2[Dd];
__device__ float g_c0;
__device__ float g_mean[Rr], g_inv[Rr];      // LN stats
// per-d-half partial reductions (half 0: cols 0..127, half 1: cols 128..255)
__device__ float g_pd[2*Rr], g_pm[2*Rr], g_pa1[2*Rr], g_pa2[2*Rr];
__device__ float g_diag[Rr];
__device__ double g_l[Rr], g_P[Rr];
__device__ int g_lo[Rr], g_hi[Rr];

// ------------------- K1: prologue = LN stats (1024) + M (256) + bias (1) ---
__global__ void prologue_kernel(const float* __restrict__ ctx,
                                const float* __restrict__ Wq,
                                const float* __restrict__ Wk,
                                const float* __restrict__ bq,
                                const float* __restrict__ bk) {
    int bid = blockIdx.x;
    int t = threadIdx.x;
    if (bid < 1024) {
        int w = t >> 5, lane = t & 31;
        int r = bid * 8 + w;
        const float* src = ctx + (size_t)r * Dd;
        float4 v0 = *(const float4*)&src[lane*4];
        float4 v1 = *(const float4*)&src[128 + lane*4];
        float s = v0.x+v0.y+v0.z+v0.w + v1.x+v1.y+v1.z+v1.w;
        #pragma unroll
        for (int o = 16; o; o >>= 1) s += __shfl_xor_sync(0xffffffffu, s, o);
        float mean = s * (1.0f/Dd);
        float d0x=v0.x-mean, d0y=v0.y-mean, d0z=v0.z-mean, d0w=v0.w-mean;
        float d1x=v1.x-mean, d1y=v1.y-mean, d1z=v1.z-mean, d1w=v1.w-mean;
        float sq = d0x*d0x+d0y*d0y+d0z*d0z+d0w*d0w + d1x*d1x+d1y*d1y+d1z*d1z+d1w*d1w;
        #pragma unroll
        for (int o = 16; o; o >>= 1) sq += __shfl_xor_sync(0xffffffffu, sq, o);
        if (lane == 0) {
            g_mean[r] = mean;
            g_inv[r] = 1.0f / (sqrtf(sq * (1.0f/(Dd-1))) + 1e-6f);
        }
    } else if (bid < 1280) {
        __shared__ float sq[16][17], sk[16][17];
        int mb = bid - 1024;
        int bx = mb & 15, by = mb >> 4;
        int tx = t & 15, ty = t >> 4;
        float acc = 0.f;
        for (int f0 = 0; f0 < Dd; f0 += 16) {
            sq[ty][tx] = Wq[(f0+ty)*Dd + by*16 + tx];
            sk[ty][tx] = Wk[(f0+ty)*Dd + bx*16 + tx];
            __syncthreads();
            #pragma unroll
            for (int f = 0; f < 16; ++f) acc += sq[f][ty] * sk[f][tx];
            __syncthreads();
        }
        g_M[(by*16+ty)*Dd + bx*16 + tx] = acc;
    } else {
        __shared__ float red[256];
        float a1 = 0.f, a2 = 0.f;
        for (int f = 0; f < Dd; ++f) {
            a1 += Wq[f*Dd + t] * bk[f];
            a2 += Wk[f*Dd + t] * bq[f];
        }
        g_c1[t] = a1; g_c2[t] = a2;
        red[t] = bq[t] * bk[t];
        __syncthreads();
        for (int s = 128; s; s >>= 1) { if (t < s) red[t] += red[t+s]; __syncthreads(); }
        if (t == 0) g_c0 = red[0];
    }
}

// ------------------- helpers -----------------------------------------------
__device__ __forceinline__ float4 ln4(float4 v, float4 l4, float4 b4, float mn, float iv) {
    return make_float4(l4.x*iv*(v.x-mn)+b4.x, l4.y*iv*(v.y-mn)+b4.y,
                       l4.z*iv*(v.z-mn)+b4.z, l4.w*iv*(v.w-mn)+b4.w);
}
__device__ __forceinline__ float dot4(float4 a, float4 b) {
    return a.x*b.x + a.y*b.y + a.z*b.z + a.w*b.w;
}

// ------------------- K2: GEMM + fused dot-reductions -----------------------
// U = X M^T computed in registers; epilogue produces per-d-half partials of
// dotp[r]=x_r.u_{r+1}, dotm[r]=x_r.u_{r-1}, A1[r]=x_r.c1, A2[r]=x_r.c2.
__global__ void __launch_bounds__(256) gemm_kernel(const float* __restrict__ ctx,
                                                   const float* __restrict__ la,
                                                   const float* __restrict__ lb) {
    __shared__ __align__(16) float As[16][132];
    __shared__ __align__(16) float Bs[16][132];
    int tid = threadIdx.x;
    int tx = tid & 15;
    int ty = tid >> 4;
    int d0 = blockIdx.x * 128;
    int r0 = blockIdx.y * 128;

    int rowL[2], segL[2];
    float mnL[2], ivL[2];
    #pragma unroll
    for (int s = 0; s < 2; ++s) {
        int idx = tid + s*256;
        rowL[s] = idx >> 2; segL[s] = (idx & 3) * 4;
        mnL[s] = g_mean[r0 + rowL[s]];
        ivL[s] = g_inv[r0 + rowL[s]];
    }

    float acc[8][8] = {};
    float4 pa[2], pb[2];

    #pragma unroll
    for (int s = 0; s < 2; ++s) {
        float4 v  = *(const float4*)&ctx[(size_t)(r0+rowL[s])*Dd + segL[s]];
        float4 l4 = *(const float4*)&la[segL[s]];
        float4 b4 = *(const float4*)&lb[segL[s]];
        pa[s] = ln4(v, l4, b4, mnL[s], ivL[s]);
        pb[s] = *(const float4*)&g_M[(size_t)(d0+rowL[s])*Dd + segL[s]];
    }

    for (int e0 = 0; e0 < Dd; e0 += 16) {
        #pragma unroll
        for (int s = 0; s < 2; ++s) {
            int row = rowL[s], seg = segL[s];
            As[seg+0][row] = pa[s].x; As[seg+1][row] = pa[s].y;
            As[seg+2][row] = pa[s].z; As[seg+3][row] = pa[s].w;
            Bs[seg+0][row] = pb[s].x; Bs[seg+1][row] = pb[s].y;
            Bs[seg+2][row] = pb[s].z; Bs[seg+3][row] = pb[s].w;
        }
        __syncthreads();
        if (e0 + 16 < Dd) {
            #pragma unroll
            for (int s = 0; s < 2; ++s) {
                int e = e0 + 16 + segL[s];
                float4 v  = *(const float4*)&ctx[(size_t)(r0+rowL[s])*Dd + e];
                float4 l4 = *(const float4*)&la[e];
                float4 b4 = *(const float4*)&lb[e];
                pa[s] = ln4(v, l4, b4, mnL[s], ivL[s]);
                pb[s] = *(const float4*)&g_M[(size_t)(d0+rowL[s])*Dd + e];
            }
        }
        #pragma unroll
        for (int k = 0; k < 16; ++k) {
            float4 a0 = *(const float4*)&As[k][ty*4];
            float4 a1 = *(const float4*)&As[k][ty*4 + 64];
            float4 b0 = *(const float4*)&Bs[k][tx*4];
            float4 b1 = *(const float4*)&Bs[k][tx*4 + 64];
            float av[8] = {a0.x,a0.y,a0.z,a0.w, a1.x,a1.y,a1.z,a1.w};
            float bv[8] = {b0.x,b0.y,b0.z,b0.w, b1.x,b1.y,b1.z,b1.w};
            #pragma unroll
            for (int i2 = 0; i2 < 8; ++i2)
                #pragma unroll
                for (int j2 = 0; j2 < 8; ++j2) acc[i2][j2] += av[i2]*bv[j2];
        }
        __syncthreads();
    }

    // ---- epilogue: fused per-row reductions over this block's 128 cols ----
    int cA = d0 + tx*4, cB = d0 + 64 + tx*4;
    float4 laA = *(const float4*)&la[cA];
    float4 laB = *(const float4*)&la[cB];
    float4 lbA = *(const float4*)&lb[cA];
    float4 lbB = *(const float4*)&lb[cB];
    float4 c1A = *(const float4*)&g_c1[cA];
    float4 c1B = *(const float4*)&g_c1[cB];
    float4 c2A = *(const float4*)&g_c2[cA];
    float4 c2B = *(const float4*)&g_c2[cB];
    size_t pbase = (size_t)blockIdx.x * Rr;

    #pragma unroll
    for (int ri = 0; ri < 2; ++ri) {
        #pragma unroll
        for (int i2 = 0; i2 < 4; ++i2) {
            int row = r0 + ri*64 + ty*4 + i2;
            const float* u = acc[ri*4 + i2];

            float mn = g_mean[row], iv = g_inv[row];
            float4 xA = ln4(*(const float4*)&ctx[(size_t)row*Dd + cA], laA, lbA, mn, iv);
            float4 xB = ln4(*(const float4*)&ctx[(size_t)row*Dd + cB], laB, lbB, mn, iv);
            float pa1 = dot4(xA, c1A) + dot4(xB, c1B);
            float pa2 = dot4(xA, c2A) + dot4(xB, c2B);

            int rp = (row + 1 < Rr) ? row + 1 : Rr - 1;
            float mnp = g_mean[rp], ivp = g_inv[rp];
            float4 ppA = ln4(*(const float4*)&ctx[(size_t)rp*Dd + cA], laA, lbA, mnp, ivp);
            float4 ppB = ln4(*(const float4*)&ctx[(size_t)rp*Dd + cB], laB, lbB, mnp, ivp);
            float pd = u[0]*ppA.x + u[1]*ppA.y + u[2]*ppA.z + u[3]*ppA.w
                     + u[4]*ppB.x + u[5]*ppB.y + u[6]*ppB.z + u[7]*ppB.w;

            int rm = (row - 1 >= 0) ? row - 1 : 0;
            float mnm = g_mean[rm], ivm = g_inv[rm];
            float4 pmA = ln4(*(const float4*)&ctx[(size_t)rm*Dd + cA], laA, lbA, mnm, ivm);
            float4 pmB = ln4(*(const float4*)&ctx[(size_t)rm*Dd + cB], laB, lbB, mnm, ivm);
            float pmv = u[0]*pmA.x + u[1]*pmA.y + u[2]*pmA.z + u[3]*pmA.w
                      + u[4]*pmB.x + u[5]*pmB.y + u[6]*pmB.z + u[7]*pmB.w;

            #pragma unroll
            for (int o = 1; o < 16; o <<= 1) {
                pd  += __shfl_xor_sync(0xffffffffu, pd,  o);
                pmv += __shfl_xor_sync(0xffffffffu, pmv, o);
                pa1 += __shfl_xor_sync(0xffffffffu, pa1, o);
                pa2 += __shfl_xor_sync(0xffffffffu, pa2, o);
            }
            if (tx == 0) {
                g_pd[pbase + row]  = pd;
                g_pm[pbase + row]  = pmv;
                g_pa1[pbase + row] = pa1;
                g_pa2[pbase + row] = pa2;
            }
        }
    }
}

// ------------------- probs helper (sums the two d-half partials) -----------
__device__ __forceinline__ void probs(const int* __restrict__ ebase, int i, int r,
                                      float& pp, float& pm, float& ps) {
    bool ap = (i < Ss-1) && (ebase[(size_t)i*Ss + i + 1] != 0);
    bool am = (i > 0)    && (ebase[(size_t)i*Ss + i - 1] != 0);
    if (!ap && !am) { pp = pm = ps = 1.0f/(float)Ss; return; }
    ps = 0.f;
    if (ap && am) {
        float c0 = g_c0;
        float dotp = g_pd[r] + g_pd[Rr + r];
        float dotm = g_pm[r] + g_pm[Rr + r];
        float a1   = g_pa1[r] + g_pa1[Rr + r];
        float a2p  = g_pa2[r+1] + g_pa2[Rr + r+1];
        float a2m  = g_pa2[r-1] + g_pa2[Rr + r-1];
        float sp = (dotp + a1 + a2p + c0) * (1.0f/256.0f);
        float sm = (dotm + a1 + a2m + c0) * (1.0f/256.0f);
        float m = fmaxf(sp, sm);
        float ep = expf(sp - m), em = expf(sm - m);
        float inv = 1.0f/(ep + em);
        pp = ep*inv; pm = em*inv;
    } else if (ap) { pp = 1.f; pm = 0.f; }
    else           { pp = 0.f; pm = 1.f; }
}

// ------------------- K3: wide probs + log + diag ---------------------------
__global__ void lprob_kernel(const int* __restrict__ eos,
                             const float* __restrict__ prior) {
    int r = blockIdx.x*64 + threadIdx.x;
    if (r >= Rr) return;
    int b = r >> 11, i = r & (Ss-1);
    const int* ebase = eos + (size_t)b*Ss*Ss;
    const float* pbase = prior + (size_t)b*Ss*Ss;

    float pp, pm, ps;
    probs(ebase, i, r, pp, pm, ps);

    if (i < Ss-1) {
        float pp2, pm2, ps2;
        probs(ebase, i+1, r+1, pp2, pm2, ps2);
        float n1 = sqrtf(pp*pm2 + 1e-9f);
        float pr = pbase[(size_t)i*Ss + i + 1];
        float nb = pr + (1.0f - pr)*n1;
        g_l[r] = log((double)nb + 1e-9);
    } else {
        g_l[r] = 0.0;
    }
    float nd = sqrtf(ps*ps + 1e-9f);
    float pr = pbase[(size_t)i*Ss + i];
    g_diag[r] = pr + (1.0f - pr)*nd;
}

// ------------------- K4: shuffle-based exclusive scan (f64) ----------------
__global__ void scan_kernel() {
    __shared__ double wsum[32];
    int b = blockIdx.x, t = threadIdx.x;
    int lane = t & 31, w = t >> 5;
    int base = b*Ss;
    double l0 = g_l[base + 2*t];
    double l1 = g_l[base + 2*t + 1];
    double s = l0 + l1;
    double v = s;
    #pragma unroll
    for (int o = 1; o < 32; o <<= 1) {
        double n = __shfl_up_sync(0xffffffffu, v, o);
        if (lane >= o) v += n;
    }
    if (lane == 31) wsum[w] = v;
    __syncthreads();
    if (w == 0) {
        double x = wsum[lane];
        #pragma unroll
        for (int o = 1; o < 32; o <<= 1) {
            double n = __shfl_up_sync(0xffffffffu, x, o);
            if (lane >= o) x += n;
        }
        wsum[lane] = x;
    }
    __syncthreads();
    double off = (w > 0) ? wsum[w-1] : 0.0;
    double excl = off + v - s;
    g_P[base + 2*t]     = excl;
    g_P[base + 2*t + 1] = excl + l0;
}

// ------------------- K5: wide band search (P in L2) ------------------------
__global__ void band_kernel() {
    int r = blockIdx.x*1024 + threadIdx.x;
    int b = r >> 11, i = r & (Ss-1);
    const double* P = g_P + b*Ss;
    double Pi = P[i];
    const double T = 46.0;

    int lo2 = i, hi2 = Ss-1;
    while (lo2 < hi2) {
        int mid = (lo2 + hi2 + 1) >> 1;
        if (Pi - P[mid] <= T) lo2 = mid; else hi2 = mid - 1;
    }
    int a = 0, b2 = i;
    while (a < b2) {
        int mid = (a + b2) >> 1;
        if (P[mid] - Pi <= T) b2 = mid; else a = mid + 1;
    }
    g_lo[r] = a; g_hi[r] = lo2;
}

// ------------------- K6: banded output, 4 rows/block, float4 ---------------
__global__ void out_kernel(float* __restrict__ out) {
    int r0 = blockIdx.x * 4;
    #pragma unroll
    for (int rr = 0; rr < 4; ++rr) {
        int r = r0 + rr;
        int b = r >> 11, i = r & (Ss-1);
        const double* P = g_P + b*Ss;
        double Pi = P[i];
        int lo = g_lo[r], hi = g_hi[r];
        float dg = g_diag[r];
        float* orow = out + (size_t)r*Ss;
        #pragma unroll
        for (int s = 0; s < 2; ++s) {
            int t = threadIdx.x + s*256;
            int j0 = t*4;
            float4 o;
            if (j0 + 3 < lo || j0 > hi) {
                o = make_float4(1e-9f, 1e-9f, 1e-9f, 1e-9f);
            } else {
                float v[4];
                #pragma unroll
                for (int q = 0; q < 4; ++q) {
                    int j = j0 + q;
                    float x;
                    if (j < lo || j > hi) x = 1e-9f;
                    else if (j == i)      x = dg;
                    else {
                        double e = (j > i) ? (P[j] - Pi) : (Pi - P[j]);
                        x = expf((float)e) + 1e-9f;
                    }
                    v[q] = x;
                }
                o = make_float4(v[0], v[1], v[2], v[3]);
            }
            *(float4*)&orow[j0] = o;
        }
    }
}

// ------------------- launch -------------------------------------------------
extern "C" void kernel_launch(void* const* d_in, const int* in_sizes, int n_in,
                              void* d_out, int out_size) {
    const float* ctx   = (const float*)d_in[0];
    const float* prior = (const float*)d_in[1];
    const float* Wq    = (const float*)d_in[2];
    const float* bq    = (const float*)d_in[3];
    const float* Wk    = (const float*)d_in[4];
    const float* bk    = (const float*)d_in[5];
    const float* la    = (const float*)d_in[6];
    const float* lb    = (const float*)d_in[7];
    const int*   eos   = (const int*)d_in[8];
    float* out = (float*)d_out;

    prologue_kernel<<<1281, 256>>>(ctx, Wq, Wk, bq, bk);
    gemm_kernel<<<dim3(2, Rr/128), 256>>>(ctx, la, lb);
    lprob_kernel<<<Rr/64, 64>>>(eos, prior);
    scan_kernel<<<Bb, 1024>>>();
    band_kernel<<<Rr/1024, 1024>>>();
    out_kernel<<<Rr/4, 256>>>(out);
}